// round 2
// baseline (speedup 1.0000x reference)
#include <cuda_runtime.h>

#define NNODES 50000
#define NEDGES 800000
#define EPS_BN 1e-5f

// ---------------- scratch (static device globals; no allocation in launch) ----
__device__ __align__(16) float g_self[NNODES * 64];
__device__ __align__(16) float g_bsum[NNODES * 64];
__device__ __align__(16) float g_esum[NNODES * 64];
__device__ __align__(16) float g_bmax[NNODES * 64];
__device__ __align__(16) float g_emax[NNODES * 64];
__device__ __align__(16) float g_mxraw[NNODES * 64];
__device__ __align__(16) float g_gath[NNODES * 128];
__device__ int g_deg[NNODES];
__device__ int g_degin[NNODES];
__device__ int g_off[NNODES + 1];
__device__ int g_cur[NNODES];
__device__ int g_csr[NEDGES];
__device__ double g_S1[64];
__device__ double g_S2[64];
__device__ double g_Su1[128];
__device__ double g_Su2[128];
__device__ unsigned g_minenc;
__device__ float g_a[64];
__device__ float g_c[64];
__device__ float g_minval;
__device__ __align__(16) float g_Wp[128 * 64];
__device__ __align__(16) float g_dbias[64];
__device__ int g_is64;

// ---------------- helpers ----------------------------------------------------
__device__ __forceinline__ unsigned enc_f32(float f) {
    unsigned u = __float_as_uint(f);
    return (u & 0x80000000u) ? ~u : (u | 0x80000000u);
}
__device__ __forceinline__ float dec_f32(unsigned u) {
    unsigned b = (u & 0x80000000u) ? (u & 0x7FFFFFFFu) : ~u;
    return __uint_as_float(b);
}
__device__ __forceinline__ int clampN(int v, int N) {
    return min(max(v, 0), N - 1);
}

// ---------------- k_zero: clear accumulators + detect edge dtype --------------
__global__ void k_zero(const void* eidx) {
    int tid = blockIdx.x * blockDim.x + threadIdx.x;
    int stride = gridDim.x * blockDim.x;
    for (int i = tid; i < NNODES; i += stride) { g_deg[i] = 0; g_degin[i] = 0; }
    if (tid < 64) { g_S1[tid] = 0.0; g_S2[tid] = 0.0; }
    if (tid < 128) { g_Su1[tid] = 0.0; g_Su2[tid] = 0.0; }
    if (tid == 0) {
        g_minenc = 0xFFFFFFFFu;
        // int64 edge_index has zero high words; 64 consecutive zero odd-slots
        // from random int32 node ids is essentially impossible.
        const int* p = (const int*)eidx;
        int is64 = 1;
        for (int k = 0; k < 64; k++) {
            if (p[2 * k + 1] != 0) { is64 = 0; break; }
        }
        g_is64 = is64;
    }
}

// ---------------- k_hist: out/in degree histogram -----------------------------
__global__ void k_hist(const void* eidx, int E, int N) {
    int is64 = g_is64;
    const long long* p64 = (const long long*)eidx;
    const int* p32 = (const int*)eidx;
    for (int e = blockIdx.x * blockDim.x + threadIdx.x; e < E;
         e += gridDim.x * blockDim.x) {
        int b, en;
        if (is64) { b = (int)p64[e]; en = (int)p64[E + e]; }
        else      { b = p32[e];      en = p32[E + e]; }
        b = clampN(b, N); en = clampN(en, N);
        atomicAdd(&g_deg[b], 1);
        atomicAdd(&g_degin[en], 1);
    }
}

// ---------------- k_gemm: nb = n_feat @ W_b + b_b -> 5 compact chunk arrays ---
// 64x64 tile, BK=16, 256 threads, 4x4 register microtile.
__global__ void k_gemm(const float* __restrict__ A, const float* __restrict__ W,
                       const float* __restrict__ bias, int N) {
    __shared__ float As[16][65];
    __shared__ float Bs[16][64];
    int chunk = blockIdx.x;            // 0..4 -> self,bsum,esum,bmax,emax
    int row0 = blockIdx.y * 64;
    int tid = threadIdx.x;
    int tx = tid & 15, ty = tid >> 4;
    int n0 = chunk * 64;
    float acc[4][4];
#pragma unroll
    for (int i = 0; i < 4; i++)
#pragma unroll
        for (int j = 0; j < 4; j++) acc[i][j] = 0.f;

    for (int k0 = 0; k0 < 128; k0 += 16) {
#pragma unroll
        for (int l = 0; l < 4; l++) {
            int i = tid + l * 256;
            int m = i >> 4, k = i & 15;
            int r = row0 + m;
            As[k][m] = (r < N) ? A[(size_t)r * 128 + k0 + k] : 0.f;
        }
#pragma unroll
        for (int l = 0; l < 4; l++) {
            int i = tid + l * 256;
            int k = i >> 6, n = i & 63;
            Bs[k][n] = W[(size_t)(k0 + k) * 320 + n0 + n];
        }
        __syncthreads();
#pragma unroll
        for (int kk = 0; kk < 16; kk++) {
            float a[4], b[4];
#pragma unroll
            for (int i = 0; i < 4; i++) a[i] = As[kk][ty * 4 + i];
#pragma unroll
            for (int j = 0; j < 4; j++) b[j] = Bs[kk][tx * 4 + j];
#pragma unroll
            for (int i = 0; i < 4; i++)
#pragma unroll
                for (int j = 0; j < 4; j++) acc[i][j] += a[i] * b[j];
        }
        __syncthreads();
    }
    float* outp = (chunk == 0) ? g_self : (chunk == 1) ? g_bsum
                : (chunk == 2) ? g_esum : (chunk == 3) ? g_bmax : g_emax;
#pragma unroll
    for (int i = 0; i < 4; i++) {
        int r = row0 + ty * 4 + i;
        if (r < N) {
#pragma unroll
            for (int j = 0; j < 4; j++) {
                int c = tx * 4 + j;
                outp[(size_t)r * 64 + c] = acc[i][j] + bias[n0 + c];
            }
        }
    }
}

// ---------------- k_scan: exclusive scan of degrees -> CSR offsets + cursor ---
__global__ void k_scan(int N) {
    __shared__ int sh[1024];
    int t = threadIdx.x;
    int chunk = (N + 1023) / 1024;
    int lo = t * chunk, hi = min(lo + chunk, N);
    int s = 0;
    for (int i = lo; i < hi; i++) s += g_deg[i];
    sh[t] = s;
    __syncthreads();
    for (int st = 1; st < 1024; st <<= 1) {
        int v = (t >= st) ? sh[t - st] : 0;
        __syncthreads();
        sh[t] += v;
        __syncthreads();
    }
    int run = (t > 0) ? sh[t - 1] : 0;
    for (int i = lo; i < hi; i++) {
        g_off[i] = run;
        g_cur[i] = run;
        run += g_deg[i];
    }
    if (t == 1023) g_off[N] = sh[1023];
}

// ---------------- k_scatter: fill CSR adjacency -------------------------------
__global__ void k_scatter(const void* eidx, int E, int N) {
    int is64 = g_is64;
    const long long* p64 = (const long long*)eidx;
    const int* p32 = (const int*)eidx;
    for (int e = blockIdx.x * blockDim.x + threadIdx.x; e < E;
         e += gridDim.x * blockDim.x) {
        int b, en;
        if (is64) { b = (int)p64[e]; en = (int)p64[E + e]; }
        else      { b = p32[e];      en = p32[E + e]; }
        b = clampN(b, N); en = clampN(en, N);
        int pos = atomicAdd(&g_cur[b], 1);
        if (pos < E) g_csr[pos] = en;
    }
}

// ---------------- k_nodeA: pass 1 -------------------------------------------
// Per node (one warp, 2 features/lane as float2):
//   segsum/segmax/segmin of gathered e_sum / e_max rows.
//   -> mx_raw = b_max + segmax(e_max)
//   -> global min_val candidate = min_f(b_max + segmin(e_max))
//   -> BN(ef_sum) stats: S1 = sum, S2 = sum of squares via
//        degout*b + degin*e  and  degout*b^2 + 2*b*segsum(e) + degin*e^2
__global__ void k_nodeA(int N) {
    int lane = threadIdx.x & 31;
    int warp = (blockIdx.x * blockDim.x + threadIdx.x) >> 5;
    int nwarps = (gridDim.x * blockDim.x) >> 5;
    int f = 2 * lane;

    float S1a = 0.f, S1b = 0.f, S2a = 0.f, S2b = 0.f;
    float lmin = 1e30f;

    for (int n = warp; n < N; n += nwarps) {
        int off = g_off[n];
        int dg = g_off[n + 1] - off;
        float2 b = *(const float2*)&g_bsum[n * 64 + f];
        float2 bm = *(const float2*)&g_bmax[n * 64 + f];
        float ssx = 0.f, ssy = 0.f;
        float mxx = -1e30f, mxy = -1e30f;
        float mnx = 1e30f, mny = 1e30f;

        for (int j0 = 0; j0 < dg; j0 += 32) {
            int idx = (j0 + lane < dg) ? g_csr[off + j0 + lane] : 0;
            int cnt = min(32, dg - j0);
            for (int j = 0; j < cnt; j++) {
                int nd = __shfl_sync(0xFFFFFFFFu, idx, j);
                float2 e = *(const float2*)&g_esum[nd * 64 + f];
                float2 m = *(const float2*)&g_emax[nd * 64 + f];
                ssx += e.x; ssy += e.y;
                mxx = fmaxf(mxx, m.x); mxy = fmaxf(mxy, m.y);
                mnx = fminf(mnx, m.x); mny = fminf(mny, m.y);
            }
        }
        float2 mxo; mxo.x = bm.x + mxx; mxo.y = bm.y + mxy;
        *(float2*)&g_mxraw[n * 64 + f] = mxo;
        if (dg > 0) lmin = fminf(lmin, fminf(bm.x + mnx, bm.y + mny));

        float dco = (float)dg;
        float dci = (float)g_degin[n];
        float2 en = *(const float2*)&g_esum[n * 64 + f];
        S1a += dco * b.x + dci * en.x;
        S1b += dco * b.y + dci * en.y;
        S2a += dco * b.x * b.x + 2.f * b.x * ssx + dci * en.x * en.x;
        S2b += dco * b.y * b.y + 2.f * b.y * ssy + dci * en.y * en.y;
    }
    atomicAdd(&g_S1[f], (double)S1a);
    atomicAdd(&g_S1[f + 1], (double)S1b);
    atomicAdd(&g_S2[f], (double)S2a);
    atomicAdd(&g_S2[f + 1], (double)S2b);
#pragma unroll
    for (int s = 16; s; s >>= 1)
        lmin = fminf(lmin, __shfl_xor_sync(0xFFFFFFFFu, lmin, s));
    if (lane == 0) atomicMin(&g_minenc, enc_f32(lmin));
}

// ---------------- k_params1: edge-BN affine params + min_val ------------------
__global__ void k_params1(const float* __restrict__ gamma,
                          const float* __restrict__ beta, double invE) {
    int fidx = threadIdx.x;  // 64 threads
    double mu = g_S1[fidx] * invE;
    double var = g_S2[fidx] * invE - mu * mu;
    float a = gamma[fidx] * rsqrtf((float)var + EPS_BN);
    g_a[fidx] = a;
    g_c[fidx] = beta[fidx] - (float)mu * a;
    if (fidx == 0) g_minval = dec_f32(g_minenc);
}

// ---------------- k_nodeB: pass 2 -------------------------------------------
// Per node: sum_agg = seg_sum(relu(a*(b_sum+e_sum[end])+c));
// gathered = [mx | sum_agg]; accumulate node-BN stats over gathered.
__global__ void k_nodeB(int N) {
    int lane = threadIdx.x & 31;
    int warp = (blockIdx.x * blockDim.x + threadIdx.x) >> 5;
    int nwarps = (gridDim.x * blockDim.x) >> 5;
    int f = 2 * lane;

    float a0 = g_a[f], a1 = g_a[f + 1];
    float c0 = g_c[f], c1 = g_c[f + 1];
    float minv = g_minval;
    float su1[4] = {0.f, 0.f, 0.f, 0.f};
    float su2[4] = {0.f, 0.f, 0.f, 0.f};

    for (int n = warp; n < N; n += nwarps) {
        int off = g_off[n];
        int dg = g_off[n + 1] - off;
        float2 b = *(const float2*)&g_bsum[n * 64 + f];
        float s0 = 0.f, s1 = 0.f;
        for (int j0 = 0; j0 < dg; j0 += 32) {
            int idx = (j0 + lane < dg) ? g_csr[off + j0 + lane] : 0;
            int cnt = min(32, dg - j0);
            for (int j = 0; j < cnt; j++) {
                int nd = __shfl_sync(0xFFFFFFFFu, idx, j);
                float2 e = *(const float2*)&g_esum[nd * 64 + f];
                s0 += fmaxf(0.f, fmaf(a0, b.x + e.x, c0));
                s1 += fmaxf(0.f, fmaf(a1, b.y + e.y, c1));
            }
        }
        float2 m;
        if (dg > 0) m = *(const float2*)&g_mxraw[n * 64 + f];
        else { m.x = minv; m.y = minv; }

        *(float2*)&g_gath[n * 128 + f] = m;
        float2 sv; sv.x = s0; sv.y = s1;
        *(float2*)&g_gath[n * 128 + 64 + f] = sv;

        su1[0] += m.x; su2[0] += m.x * m.x;
        su1[1] += m.y; su2[1] += m.y * m.y;
        su1[2] += s0;  su2[2] += s0 * s0;
        su1[3] += s1;  su2[3] += s1 * s1;
    }
    atomicAdd(&g_Su1[f], (double)su1[0]);
    atomicAdd(&g_Su2[f], (double)su2[0]);
    atomicAdd(&g_Su1[f + 1], (double)su1[1]);
    atomicAdd(&g_Su2[f + 1], (double)su2[1]);
    atomicAdd(&g_Su1[64 + f], (double)su1[2]);
    atomicAdd(&g_Su2[64 + f], (double)su2[2]);
    atomicAdd(&g_Su1[64 + f + 1], (double)su1[3]);
    atomicAdd(&g_Su2[64 + f + 1], (double)su2[3]);
}

// ---------------- k_params2: fold node-BN into update GEMM -------------------
// W'[k][j] = a_u[k]*W_u[k][j];  d[j] = sum_k c_u[k]*W_u[k][j]
__global__ void k_params2(const float* __restrict__ gamma_u,
                          const float* __restrict__ beta_u,
                          const float* __restrict__ W_u, double invN) {
    __shared__ float sc[128];
    int k = threadIdx.x;  // 128 threads
    double mu = g_Su1[k] * invN;
    double var = g_Su2[k] * invN - mu * mu;
    float au = gamma_u[k] * rsqrtf((float)var + EPS_BN);
    float cu = beta_u[k] - (float)mu * au;
    sc[k] = cu;
    for (int j = 0; j < 64; j++) g_Wp[k * 64 + j] = au * W_u[k * 64 + j];
    __syncthreads();
    if (k < 64) {
        float d = 0.f;
        for (int kk = 0; kk < 128; kk++) d += sc[kk] * W_u[kk * 64 + k];
        g_dbias[k] = d;
    }
}

// ---------------- k_final: out = self_f + relu(gathered @ W' + d) -------------
__global__ void k_final(float* __restrict__ out, int N) {
    __shared__ __align__(16) float sW[128 * 64];
    __shared__ __align__(16) float sG[16 * 128];
    __shared__ __align__(16) float sd[64];
    int tid = threadIdx.x;
    for (int i = tid; i < 128 * 64; i += 256) sW[i] = g_Wp[i];
    if (tid < 64) sd[tid] = g_dbias[tid];
    __syncthreads();

    int ni = tid >> 4;       // 0..15 node slot
    int jx = tid & 15;       // 0..15 -> 4 output cols
    int tiles = (N + 15) / 16;
    const float4* W4 = (const float4*)sW;

    for (int t = blockIdx.x; t < tiles; t += gridDim.x) {
        int n0 = t * 16;
        __syncthreads();
        for (int i = tid; i < 16 * 128; i += 256) {
            int gi = n0 * 128 + i;
            sG[i] = (gi < N * 128) ? g_gath[gi] : 0.f;
        }
        __syncthreads();

        float4 acc = {0.f, 0.f, 0.f, 0.f};
#pragma unroll 8
        for (int k = 0; k < 128; k++) {
            float gv = sG[ni * 128 + k];
            float4 w = W4[k * 16 + jx];
            acc.x += gv * w.x;
            acc.y += gv * w.y;
            acc.z += gv * w.z;
            acc.w += gv * w.w;
        }
        int n = n0 + ni;
        if (n < N) {
            float4 dv = ((const float4*)sd)[jx];
            const float4 sf = *(const float4*)&g_self[(size_t)n * 64 + jx * 4];
            float4 o;
            o.x = sf.x + fmaxf(0.f, acc.x + dv.x);
            o.y = sf.y + fmaxf(0.f, acc.y + dv.y);
            o.z = sf.z + fmaxf(0.f, acc.z + dv.z);
            o.w = sf.w + fmaxf(0.f, acc.w + dv.w);
            *(float4*)&out[(size_t)n * 64 + jx * 4] = o;
        }
    }
}

// ---------------- launch ------------------------------------------------------
extern "C" void kernel_launch(void* const* d_in, const int* in_sizes, int n_in,
                              void* d_out, int out_size) {
    const float* n_feat  = (const float*)d_in[0];
    const void*  eidx    = d_in[1];
    const float* W_b     = (const float*)d_in[2];
    const float* b_b     = (const float*)d_in[3];
    const float* gamma_g = (const float*)d_in[4];
    const float* beta_g  = (const float*)d_in[5];
    const float* gamma_u = (const float*)d_in[6];
    const float* beta_u  = (const float*)d_in[7];
    const float* W_u     = (const float*)d_in[8];
    float* out = (float*)d_out;

    int N = in_sizes[0] / 128;
    int E = in_sizes[1] / 2;

    k_zero<<<256, 256>>>(eidx);
    k_hist<<<2048, 256>>>(eidx, E, N);
    dim3 ggrid(5, (N + 63) / 64);
    k_gemm<<<ggrid, 256>>>(n_feat, W_b, b_b, N);
    k_scan<<<1, 1024>>>(N);
    k_scatter<<<2048, 256>>>(eidx, E, N);
    k_nodeA<<<1184, 256>>>(N);
    k_params1<<<1, 64>>>(gamma_g, beta_g, 1.0 / (double)E);
    k_nodeB<<<1184, 256>>>(N);
    k_params2<<<1, 128>>>(gamma_u, beta_u, W_u, 1.0 / (double)N);
    k_final<<<1480, 256>>>(out, N);
}

// round 3
// speedup vs baseline: 1.0775x; 1.0775x over previous
#include <cuda_runtime.h>

#define NNODES 50000
#define NEDGES 800000
#define EPS_BN 1e-5f

// ---------------- scratch (static device globals) -----------------------------
__device__ __align__(16) float g_self[NNODES * 64];
__device__ __align__(16) float g_bsum[NNODES * 64];
__device__ __align__(16) float g_esum[NNODES * 64];
__device__ __align__(16) float g_bmax[NNODES * 64];
__device__ __align__(16) float g_ea[NNODES * 128];   // interleaved (esum,emax) pairs
__device__ __align__(16) float g_mxraw[NNODES * 64];
__device__ __align__(16) float g_gath[NNODES * 128];
__device__ int g_deg[NNODES];
__device__ int g_degin[NNODES];
__device__ int g_off[NNODES + 1];
__device__ int g_cur[NNODES];
__device__ int g_csr[NEDGES];
__device__ int g_part[256];
__device__ double g_S1[64];
__device__ double g_S2[64];
__device__ double g_Su1[128];
__device__ double g_Su2[128];
__device__ unsigned g_minenc;
__device__ float g_a[64];
__device__ float g_c[64];
__device__ float g_minval;
__device__ __align__(16) float g_Wp[128 * 64];
__device__ __align__(16) float g_dbias[64];
__device__ int g_is64;

// ---------------- helpers -----------------------------------------------------
__device__ __forceinline__ unsigned enc_f32(float f) {
    unsigned u = __float_as_uint(f);
    return (u & 0x80000000u) ? ~u : (u | 0x80000000u);
}
__device__ __forceinline__ float dec_f32(unsigned u) {
    unsigned b = (u & 0x80000000u) ? (u & 0x7FFFFFFFu) : ~u;
    return __uint_as_float(b);
}
__device__ __forceinline__ int clampN(int v, int N) {
    return min(max(v, 0), N - 1);
}

// ---------------- k_zero: clear accumulators + detect edge dtype --------------
__global__ void k_zero(const void* eidx) {
    int tid = blockIdx.x * blockDim.x + threadIdx.x;
    int stride = gridDim.x * blockDim.x;
    for (int i = tid; i < NNODES; i += stride) { g_deg[i] = 0; g_degin[i] = 0; }
    if (tid < 64) { g_S1[tid] = 0.0; g_S2[tid] = 0.0; }
    if (tid < 128) { g_Su1[tid] = 0.0; g_Su2[tid] = 0.0; }
    if (blockIdx.x == 0) {
        __shared__ int nz;
        if (threadIdx.x == 0) nz = 0;
        __syncthreads();
        if (threadIdx.x < 64) {
            // int64 edge_index has zero high words; 64 zero odd-slots from
            // random int32 ids is essentially impossible.
            if (((const int*)eidx)[2 * threadIdx.x + 1] != 0) atomicAdd(&nz, 1);
        }
        __syncthreads();
        if (threadIdx.x == 0) {
            g_is64 = (nz == 0);
            g_minenc = 0xFFFFFFFFu;
        }
    }
}

// ---------------- k_hist: out/in degree histogram -----------------------------
__global__ void k_hist(const void* eidx, int E, int N) {
    int is64 = g_is64;
    const long long* p64 = (const long long*)eidx;
    const int* p32 = (const int*)eidx;
    for (int e = blockIdx.x * blockDim.x + threadIdx.x; e < E;
         e += gridDim.x * blockDim.x) {
        int b, en;
        if (is64) { b = (int)p64[e]; en = (int)p64[E + e]; }
        else      { b = p32[e];      en = p32[E + e]; }
        b = clampN(b, N); en = clampN(en, N);
        atomicAdd(&g_deg[b], 1);
        atomicAdd(&g_degin[en], 1);
    }
}

// ---------------- k_gemm: nb = n_feat @ W_b + b_b ------------------------------
// 128x128 output tile over the full [N,320] result, 8x8 microtile, BK=16.
// grid.x: 3 column tiles (c0 = 0,128,256; last half-masked). grid.y: row tiles.
__global__ void k_gemm(const float* __restrict__ A, const float* __restrict__ W,
                       const float* __restrict__ bias, int N) {
    __shared__ __align__(16) float As[16][136];
    __shared__ __align__(16) float Bs[16][136];
    int c0 = blockIdx.x * 128;
    int row0 = blockIdx.y * 128;
    int tid = threadIdx.x;
    int tx = tid & 15, ty = tid >> 4;

    float acc[8][8];
#pragma unroll
    for (int i = 0; i < 8; i++)
#pragma unroll
        for (int j = 0; j < 8; j++) acc[i][j] = 0.f;

    for (int k0 = 0; k0 < 128; k0 += 16) {
        // A slice: 128 rows x 16 k, stored transposed As[k][row]
#pragma unroll
        for (int l = 0; l < 2; l++) {
            int idx = tid + l * 256;          // 0..511 float4 slots
            int m = idx >> 2;                  // row 0..127
            int kq = idx & 3;                  // float4 within 16-k slice
            int r = row0 + m;
            float4 v = make_float4(0.f, 0.f, 0.f, 0.f);
            if (r < N) v = *(const float4*)&A[(size_t)r * 128 + k0 + kq * 4];
            As[kq * 4 + 0][m] = v.x;
            As[kq * 4 + 1][m] = v.y;
            As[kq * 4 + 2][m] = v.z;
            As[kq * 4 + 3][m] = v.w;
        }
        // B slice: 16 k x 128 cols
#pragma unroll
        for (int l = 0; l < 2; l++) {
            int idx = tid + l * 256;           // 0..511 float4 slots
            int k = idx >> 5;                  // 0..15
            int nq = idx & 31;                 // float4 within 128 cols
            float4 v = make_float4(0.f, 0.f, 0.f, 0.f);
            if (c0 + nq * 4 < 320)
                v = *(const float4*)&W[(size_t)(k0 + k) * 320 + c0 + nq * 4];
            *(float4*)&Bs[k][nq * 4] = v;
        }
        __syncthreads();
#pragma unroll
        for (int kk = 0; kk < 16; kk++) {
            float4 a0 = *(const float4*)&As[kk][ty * 8];
            float4 a1 = *(const float4*)&As[kk][ty * 8 + 4];
            float4 b0 = *(const float4*)&Bs[kk][tx * 8];
            float4 b1 = *(const float4*)&Bs[kk][tx * 8 + 4];
            float ar[8] = {a0.x, a0.y, a0.z, a0.w, a1.x, a1.y, a1.z, a1.w};
            float br[8] = {b0.x, b0.y, b0.z, b0.w, b1.x, b1.y, b1.z, b1.w};
#pragma unroll
            for (int i = 0; i < 8; i++)
#pragma unroll
                for (int j = 0; j < 8; j++) acc[i][j] += ar[i] * br[j];
        }
        __syncthreads();
    }

    // Epilogue: this thread's 8 cols all lie in one 64-col chunk.
    int cglob = c0 + tx * 8;
    if (cglob >= 320) return;
    int chunk = cglob >> 6;
    int cc = cglob & 63;
    float bv[8];
#pragma unroll
    for (int j = 0; j < 8; j++) bv[j] = bias[cglob + j];

    float* outp = (chunk == 0) ? g_self : (chunk == 1) ? g_bsum
                : (chunk == 2) ? g_esum : (chunk == 3) ? g_bmax : (float*)0;
#pragma unroll
    for (int i = 0; i < 8; i++) {
        int r = row0 + ty * 8 + i;
        if (r >= N) break;
        if (chunk == 4) {          // emax -> interleaved odd slots only
#pragma unroll
            for (int j = 0; j < 8; j++)
                g_ea[(size_t)r * 128 + 2 * (cc + j) + 1] = acc[i][j] + bv[j];
        } else if (chunk == 2) {   // esum -> compact + interleaved even slots
#pragma unroll
            for (int j = 0; j < 8; j++) {
                float v = acc[i][j] + bv[j];
                g_esum[(size_t)r * 64 + cc + j] = v;
                g_ea[(size_t)r * 128 + 2 * (cc + j)] = v;
            }
        } else {
#pragma unroll
            for (int j = 0; j < 8; j++)
                outp[(size_t)r * 64 + cc + j] = acc[i][j] + bv[j];
        }
    }
}

// ---------------- parallel exclusive scan (3 kernels) --------------------------
__global__ void k_scanA(int N) {
    __shared__ int sh[256];
    int t = threadIdx.x;
    int i = blockIdx.x * 256 + t;
    int d = (i < N) ? g_deg[i] : 0;
    sh[t] = d;
    __syncthreads();
    for (int st = 1; st < 256; st <<= 1) {
        int v = (t >= st) ? sh[t - st] : 0;
        __syncthreads();
        sh[t] += v;
        __syncthreads();
    }
    if (i < N) g_off[i] = sh[t] - d;
    if (t == 255) g_part[blockIdx.x] = sh[255];
}
__global__ void k_scanB(int nb, int N) {
    __shared__ int sh[256];
    int t = threadIdx.x;
    int d = (t < nb) ? g_part[t] : 0;
    sh[t] = d;
    __syncthreads();
    for (int st = 1; st < 256; st <<= 1) {
        int v = (t >= st) ? sh[t - st] : 0;
        __syncthreads();
        sh[t] += v;
        __syncthreads();
    }
    if (t < nb) g_part[t] = sh[t] - d;
    if (t == 255) g_off[N] = sh[255];
}
__global__ void k_scanC(int N) {
    int i = blockIdx.x * 256 + threadIdx.x;
    if (i < N) {
        int v = g_off[i] + g_part[blockIdx.x];
        g_off[i] = v;
        g_cur[i] = v;
    }
}

// ---------------- k_scatter: fill CSR adjacency -------------------------------
__global__ void k_scatter(const void* eidx, int E, int N) {
    int is64 = g_is64;
    const long long* p64 = (const long long*)eidx;
    const int* p32 = (const int*)eidx;
    for (int e = blockIdx.x * blockDim.x + threadIdx.x; e < E;
         e += gridDim.x * blockDim.x) {
        int b, en;
        if (is64) { b = (int)p64[e]; en = (int)p64[E + e]; }
        else      { b = p32[e];      en = p32[E + e]; }
        b = clampN(b, N); en = clampN(en, N);
        int pos = atomicAdd(&g_cur[b], 1);
        if (pos < E) g_csr[pos] = en;
    }
}

// ---------------- k_nodeA: pass 1 ---------------------------------------------
// One warp per node; lane owns features 2l,2l+1. Reads the interleaved
// (esum,emax) row with ONE float4 per edge, 4-edge unrolled for MLP.
__global__ void k_nodeA(int N) {
    int lane = threadIdx.x & 31;
    int warp = (blockIdx.x * blockDim.x + threadIdx.x) >> 5;
    int nwarps = (gridDim.x * blockDim.x) >> 5;
    int f = 2 * lane;

    float S1a = 0.f, S1b = 0.f, S2a = 0.f, S2b = 0.f;
    float lmin = 1e30f;

    for (int n = warp; n < N; n += nwarps) {
        int off = g_off[n];
        int dg = g_off[n + 1] - off;
        float2 b = *(const float2*)&g_bsum[n * 64 + f];
        float2 bm = *(const float2*)&g_bmax[n * 64 + f];
        float ssx = 0.f, ssy = 0.f;
        float mxx = -1e30f, mxy = -1e30f;
        float mnx = 1e30f, mny = 1e30f;

        for (int j0 = 0; j0 < dg; j0 += 32) {
            int idx = (j0 + lane < dg) ? g_csr[off + j0 + lane] : 0;
            int cnt = min(32, dg - j0);
            int j = 0;
            for (; j + 4 <= cnt; j += 4) {
                int n0 = __shfl_sync(0xFFFFFFFFu, idx, j);
                int n1 = __shfl_sync(0xFFFFFFFFu, idx, j + 1);
                int n2 = __shfl_sync(0xFFFFFFFFu, idx, j + 2);
                int n3 = __shfl_sync(0xFFFFFFFFu, idx, j + 3);
                float4 q0 = *(const float4*)&g_ea[(size_t)n0 * 128 + 4 * lane];
                float4 q1 = *(const float4*)&g_ea[(size_t)n1 * 128 + 4 * lane];
                float4 q2 = *(const float4*)&g_ea[(size_t)n2 * 128 + 4 * lane];
                float4 q3 = *(const float4*)&g_ea[(size_t)n3 * 128 + 4 * lane];
                ssx += (q0.x + q1.x) + (q2.x + q3.x);
                ssy += (q0.z + q1.z) + (q2.z + q3.z);
                mxx = fmaxf(fmaxf(mxx, q0.y), fmaxf(q1.y, fmaxf(q2.y, q3.y)));
                mxy = fmaxf(fmaxf(mxy, q0.w), fmaxf(q1.w, fmaxf(q2.w, q3.w)));
                mnx = fminf(fminf(mnx, q0.y), fminf(q1.y, fminf(q2.y, q3.y)));
                mny = fminf(fminf(mny, q0.w), fminf(q1.w, fminf(q2.w, q3.w)));
            }
            for (; j < cnt; j++) {
                int nd = __shfl_sync(0xFFFFFFFFu, idx, j);
                float4 q = *(const float4*)&g_ea[(size_t)nd * 128 + 4 * lane];
                ssx += q.x; ssy += q.z;
                mxx = fmaxf(mxx, q.y); mxy = fmaxf(mxy, q.w);
                mnx = fminf(mnx, q.y); mny = fminf(mny, q.w);
            }
        }
        float2 mxo; mxo.x = bm.x + mxx; mxo.y = bm.y + mxy;
        *(float2*)&g_mxraw[n * 64 + f] = mxo;
        if (dg > 0) lmin = fminf(lmin, fminf(bm.x + mnx, bm.y + mny));

        float dco = (float)dg;
        float dci = (float)g_degin[n];
        float2 en = *(const float2*)&g_esum[n * 64 + f];
        S1a += dco * b.x + dci * en.x;
        S1b += dco * b.y + dci * en.y;
        S2a += dco * b.x * b.x + 2.f * b.x * ssx + dci * en.x * en.x;
        S2b += dco * b.y * b.y + 2.f * b.y * ssy + dci * en.y * en.y;
    }
    atomicAdd(&g_S1[f], (double)S1a);
    atomicAdd(&g_S1[f + 1], (double)S1b);
    atomicAdd(&g_S2[f], (double)S2a);
    atomicAdd(&g_S2[f + 1], (double)S2b);
#pragma unroll
    for (int s = 16; s; s >>= 1)
        lmin = fminf(lmin, __shfl_xor_sync(0xFFFFFFFFu, lmin, s));
    if (lane == 0) atomicMin(&g_minenc, enc_f32(lmin));
}

// ---------------- k_params1: edge-BN affine params + min_val -------------------
__global__ void k_params1(const float* __restrict__ gamma,
                          const float* __restrict__ beta, double invE) {
    int fidx = threadIdx.x;  // 64 threads
    double mu = g_S1[fidx] * invE;
    double var = g_S2[fidx] * invE - mu * mu;
    float a = gamma[fidx] * rsqrtf((float)var + EPS_BN);
    g_a[fidx] = a;
    g_c[fidx] = beta[fidx] - (float)mu * a;
    if (fidx == 0) g_minval = dec_f32(g_minenc);
}

// ---------------- k_nodeB: pass 2 ---------------------------------------------
__global__ void k_nodeB(int N) {
    int lane = threadIdx.x & 31;
    int warp = (blockIdx.x * blockDim.x + threadIdx.x) >> 5;
    int nwarps = (gridDim.x * blockDim.x) >> 5;
    int f = 2 * lane;

    float a0 = g_a[f], a1 = g_a[f + 1];
    float c0 = g_c[f], c1 = g_c[f + 1];
    float minv = g_minval;
    float su1[4] = {0.f, 0.f, 0.f, 0.f};
    float su2[4] = {0.f, 0.f, 0.f, 0.f};

    for (int n = warp; n < N; n += nwarps) {
        int off = g_off[n];
        int dg = g_off[n + 1] - off;
        float2 b = *(const float2*)&g_bsum[n * 64 + f];
        float s0 = 0.f, s1 = 0.f;
        for (int j0 = 0; j0 < dg; j0 += 32) {
            int idx = (j0 + lane < dg) ? g_csr[off + j0 + lane] : 0;
            int cnt = min(32, dg - j0);
            int j = 0;
            for (; j + 4 <= cnt; j += 4) {
                int n0 = __shfl_sync(0xFFFFFFFFu, idx, j);
                int n1 = __shfl_sync(0xFFFFFFFFu, idx, j + 1);
                int n2 = __shfl_sync(0xFFFFFFFFu, idx, j + 2);
                int n3 = __shfl_sync(0xFFFFFFFFu, idx, j + 3);
                float2 e0 = *(const float2*)&g_esum[(size_t)n0 * 64 + f];
                float2 e1 = *(const float2*)&g_esum[(size_t)n1 * 64 + f];
                float2 e2 = *(const float2*)&g_esum[(size_t)n2 * 64 + f];
                float2 e3 = *(const float2*)&g_esum[(size_t)n3 * 64 + f];
                s0 += fmaxf(0.f, fmaf(a0, b.x + e0.x, c0))
                    + fmaxf(0.f, fmaf(a0, b.x + e1.x, c0))
                    + fmaxf(0.f, fmaf(a0, b.x + e2.x, c0))
                    + fmaxf(0.f, fmaf(a0, b.x + e3.x, c0));
                s1 += fmaxf(0.f, fmaf(a1, b.y + e0.y, c1))
                    + fmaxf(0.f, fmaf(a1, b.y + e1.y, c1))
                    + fmaxf(0.f, fmaf(a1, b.y + e2.y, c1))
                    + fmaxf(0.f, fmaf(a1, b.y + e3.y, c1));
            }
            for (; j < cnt; j++) {
                int nd = __shfl_sync(0xFFFFFFFFu, idx, j);
                float2 e = *(const float2*)&g_esum[(size_t)nd * 64 + f];
                s0 += fmaxf(0.f, fmaf(a0, b.x + e.x, c0));
                s1 += fmaxf(0.f, fmaf(a1, b.y + e.y, c1));
            }
        }
        float2 m;
        if (dg > 0) m = *(const float2*)&g_mxraw[n * 64 + f];
        else { m.x = minv; m.y = minv; }

        *(float2*)&g_gath[n * 128 + f] = m;
        float2 sv; sv.x = s0; sv.y = s1;
        *(float2*)&g_gath[n * 128 + 64 + f] = sv;

        su1[0] += m.x; su2[0] += m.x * m.x;
        su1[1] += m.y; su2[1] += m.y * m.y;
        su1[2] += s0;  su2[2] += s0 * s0;
        su1[3] += s1;  su2[3] += s1 * s1;
    }
    atomicAdd(&g_Su1[f], (double)su1[0]);
    atomicAdd(&g_Su2[f], (double)su2[0]);
    atomicAdd(&g_Su1[f + 1], (double)su1[1]);
    atomicAdd(&g_Su2[f + 1], (double)su2[1]);
    atomicAdd(&g_Su1[64 + f], (double)su1[2]);
    atomicAdd(&g_Su2[64 + f], (double)su2[2]);
    atomicAdd(&g_Su1[64 + f + 1], (double)su1[3]);
    atomicAdd(&g_Su2[64 + f + 1], (double)su2[3]);
}

// ---------------- k_params2: fold node-BN into update GEMM ---------------------
__global__ void k_params2(const float* __restrict__ gamma_u,
                          const float* __restrict__ beta_u,
                          const float* __restrict__ W_u, double invN) {
    __shared__ float sc[128];
    int k = threadIdx.x;  // 128 threads
    double mu = g_Su1[k] * invN;
    double var = g_Su2[k] * invN - mu * mu;
    float au = gamma_u[k] * rsqrtf((float)var + EPS_BN);
    float cu = beta_u[k] - (float)mu * au;
    sc[k] = cu;
    for (int j = 0; j < 64; j++) g_Wp[k * 64 + j] = au * W_u[k * 64 + j];
    __syncthreads();
    if (k < 64) {
        float d = 0.f;
        for (int kk = 0; kk < 128; kk++) d += sc[kk] * W_u[kk * 64 + k];
        g_dbias[k] = d;
    }
}

// ---------------- k_final: out = self_f + relu(gathered @ W' + d) --------------
__global__ void k_final(float* __restrict__ out, int N) {
    __shared__ __align__(16) float sW[128 * 64];
    __shared__ __align__(16) float sG[16 * 128];
    __shared__ __align__(16) float sd[64];
    int tid = threadIdx.x;
    for (int i = tid; i < 128 * 64; i += 256) sW[i] = g_Wp[i];
    if (tid < 64) sd[tid] = g_dbias[tid];
    __syncthreads();

    int ni = tid >> 4;
    int jx = tid & 15;
    int tiles = (N + 15) / 16;
    const float4* W4 = (const float4*)sW;

    for (int t = blockIdx.x; t < tiles; t += gridDim.x) {
        int n0 = t * 16;
        __syncthreads();
        for (int i = tid; i < 16 * 128; i += 256) {
            int gi = n0 * 128 + i;
            sG[i] = (gi < N * 128) ? g_gath[gi] : 0.f;
        }
        __syncthreads();

        float4 acc = {0.f, 0.f, 0.f, 0.f};
#pragma unroll 8
        for (int k = 0; k < 128; k++) {
            float gv = sG[ni * 128 + k];
            float4 w = W4[k * 16 + jx];
            acc.x += gv * w.x;
            acc.y += gv * w.y;
            acc.z += gv * w.z;
            acc.w += gv * w.w;
        }
        int n = n0 + ni;
        if (n < N) {
            float4 dv = ((const float4*)sd)[jx];
            const float4 sf = *(const float4*)&g_self[(size_t)n * 64 + jx * 4];
            float4 o;
            o.x = sf.x + fmaxf(0.f, acc.x + dv.x);
            o.y = sf.y + fmaxf(0.f, acc.y + dv.y);
            o.z = sf.z + fmaxf(0.f, acc.z + dv.z);
            o.w = sf.w + fmaxf(0.f, acc.w + dv.w);
            *(float4*)&out[(size_t)n * 64 + jx * 4] = o;
        }
    }
}

// ---------------- launch ------------------------------------------------------
extern "C" void kernel_launch(void* const* d_in, const int* in_sizes, int n_in,
                              void* d_out, int out_size) {
    const float* n_feat  = (const float*)d_in[0];
    const void*  eidx    = d_in[1];
    const float* W_b     = (const float*)d_in[2];
    const float* b_b     = (const float*)d_in[3];
    const float* gamma_g = (const float*)d_in[4];
    const float* beta_g  = (const float*)d_in[5];
    const float* gamma_u = (const float*)d_in[6];
    const float* beta_u  = (const float*)d_in[7];
    const float* W_u     = (const float*)d_in[8];
    float* out = (float*)d_out;

    int N = in_sizes[0] / 128;
    int E = in_sizes[1] / 2;
    int nscan = (N + 255) / 256;

    k_zero<<<256, 256>>>(eidx);
    k_hist<<<2048, 256>>>(eidx, E, N);
    dim3 ggrid(3, (N + 127) / 128);
    k_gemm<<<ggrid, 256>>>(n_feat, W_b, b_b, N);
    k_scanA<<<nscan, 256>>>(N);
    k_scanB<<<1, 256>>>(nscan, N);
    k_scanC<<<nscan, 256>>>(N);
    k_scatter<<<2048, 256>>>(eidx, E, N);
    k_nodeA<<<1184, 256>>>(N);
    k_params1<<<1, 64>>>(gamma_g, beta_g, 1.0 / (double)E);
    k_nodeB<<<1184, 256>>>(N);
    k_params2<<<1, 128>>>(gamma_u, beta_u, W_u, 1.0 / (double)N);
    k_final<<<1480, 256>>>(out, N);
}

// round 4
// speedup vs baseline: 2.7622x; 2.5634x over previous
#include <cuda_runtime.h>

#define NNODES 50000
#define NEDGES 800000
#define EPS_BN 1e-5f

// ---------------- scratch (static device globals) -----------------------------
__device__ __align__(16) float g_self[NNODES * 64];
__device__ __align__(16) float g_bsum[NNODES * 64];
__device__ __align__(16) float g_esum[NNODES * 64];
__device__ __align__(16) float g_bmax[NNODES * 64];
__device__ __align__(16) float g_ea[NNODES * 128];   // interleaved (esum,emax)
__device__ __align__(16) float g_mxraw[NNODES * 64];
__device__ __align__(16) float g_gath[NNODES * 128];
__device__ int g_deg[NNODES];
__device__ int g_degin[NNODES];
__device__ int g_off[NNODES + 1];
__device__ int g_cur[NNODES];
__device__ int g_csr[NEDGES];
__device__ int g_part[256];
__device__ double g_S1[64];
__device__ double g_S2[64];
__device__ double g_Su1[128];
__device__ double g_Su2[128];
__device__ unsigned g_minenc;
__device__ float g_a[64];
__device__ float g_c[64];
__device__ float g_minval;
__device__ __align__(16) float g_Wp[128 * 64];
__device__ __align__(16) float g_dbias[64];
__device__ int g_is64;

// ---------------- helpers -----------------------------------------------------
__device__ __forceinline__ unsigned enc_f32(float f) {
    unsigned u = __float_as_uint(f);
    return (u & 0x80000000u) ? ~u : (u | 0x80000000u);
}
__device__ __forceinline__ float dec_f32(unsigned u) {
    unsigned b = (u & 0x80000000u) ? (u & 0x7FFFFFFFu) : ~u;
    return __uint_as_float(b);
}
__device__ __forceinline__ int clampN(int v, int N) {
    return min(max(v, 0), N - 1);
}

// ---------------- k_zero: clear accumulators + detect edge dtype --------------
__global__ void k_zero(const void* eidx) {
    int tid = blockIdx.x * blockDim.x + threadIdx.x;
    int stride = gridDim.x * blockDim.x;
    for (int i = tid; i < NNODES; i += stride) { g_deg[i] = 0; g_degin[i] = 0; }
    if (tid < 64) { g_S1[tid] = 0.0; g_S2[tid] = 0.0; }
    if (tid < 128) { g_Su1[tid] = 0.0; g_Su2[tid] = 0.0; }
    if (blockIdx.x == 0) {
        __shared__ int nz;
        if (threadIdx.x == 0) nz = 0;
        __syncthreads();
        if (threadIdx.x < 64) {
            // int64 edge_index has zero high words; 64 zero odd-slots from
            // random int32 ids is essentially impossible.
            if (((const int*)eidx)[2 * threadIdx.x + 1] != 0) atomicAdd(&nz, 1);
        }
        __syncthreads();
        if (threadIdx.x == 0) {
            g_is64 = (nz == 0);
            g_minenc = 0xFFFFFFFFu;
        }
    }
}

// ---------------- k_hist: out/in degree histogram -----------------------------
__global__ void k_hist(const void* eidx, int E, int N) {
    int is64 = g_is64;
    const long long* p64 = (const long long*)eidx;
    const int* p32 = (const int*)eidx;
    for (int e = blockIdx.x * blockDim.x + threadIdx.x; e < E;
         e += gridDim.x * blockDim.x) {
        int b, en;
        if (is64) { b = (int)p64[e]; en = (int)p64[E + e]; }
        else      { b = p32[e];      en = p32[E + e]; }
        b = clampN(b, N); en = clampN(en, N);
        atomicAdd(&g_deg[b], 1);
        atomicAdd(&g_degin[en], 1);
    }
}

// ---------------- k_gemm: nb = n_feat @ W_b + b_b ------------------------------
// 128x128 output tile, 8x8 microtile, BK=16. grid.x: 3 col tiles (last masked).
__global__ void k_gemm(const float* __restrict__ A, const float* __restrict__ W,
                       const float* __restrict__ bias, int N) {
    __shared__ __align__(16) float As[16][136];
    __shared__ __align__(16) float Bs[16][136];
    int c0 = blockIdx.x * 128;
    int row0 = blockIdx.y * 128;
    int tid = threadIdx.x;
    int tx = tid & 15, ty = tid >> 4;

    float acc[8][8];
#pragma unroll
    for (int i = 0; i < 8; i++)
#pragma unroll
        for (int j = 0; j < 8; j++) acc[i][j] = 0.f;

    for (int k0 = 0; k0 < 128; k0 += 16) {
#pragma unroll
        for (int l = 0; l < 2; l++) {
            int idx = tid + l * 256;
            int m = idx >> 2;
            int kq = idx & 3;
            int r = row0 + m;
            float4 v = make_float4(0.f, 0.f, 0.f, 0.f);
            if (r < N) v = *(const float4*)&A[(size_t)r * 128 + k0 + kq * 4];
            As[kq * 4 + 0][m] = v.x;
            As[kq * 4 + 1][m] = v.y;
            As[kq * 4 + 2][m] = v.z;
            As[kq * 4 + 3][m] = v.w;
        }
#pragma unroll
        for (int l = 0; l < 2; l++) {
            int idx = tid + l * 256;
            int k = idx >> 5;
            int nq = idx & 31;
            float4 v = make_float4(0.f, 0.f, 0.f, 0.f);
            if (c0 + nq * 4 < 320)
                v = *(const float4*)&W[(size_t)(k0 + k) * 320 + c0 + nq * 4];
            *(float4*)&Bs[k][nq * 4] = v;
        }
        __syncthreads();
#pragma unroll
        for (int kk = 0; kk < 16; kk++) {
            float4 a0 = *(const float4*)&As[kk][ty * 8];
            float4 a1 = *(const float4*)&As[kk][ty * 8 + 4];
            float4 b0 = *(const float4*)&Bs[kk][tx * 8];
            float4 b1 = *(const float4*)&Bs[kk][tx * 8 + 4];
            float ar[8] = {a0.x, a0.y, a0.z, a0.w, a1.x, a1.y, a1.z, a1.w};
            float br[8] = {b0.x, b0.y, b0.z, b0.w, b1.x, b1.y, b1.z, b1.w};
#pragma unroll
            for (int i = 0; i < 8; i++)
#pragma unroll
                for (int j = 0; j < 8; j++) acc[i][j] += ar[i] * br[j];
        }
        __syncthreads();
    }

    int cglob = c0 + tx * 8;
    if (cglob >= 320) return;
    int chunk = cglob >> 6;
    int cc = cglob & 63;
    float bv[8];
#pragma unroll
    for (int j = 0; j < 8; j++) bv[j] = bias[cglob + j];

    float* outp = (chunk == 0) ? g_self : (chunk == 1) ? g_bsum
                : (chunk == 2) ? g_esum : (chunk == 3) ? g_bmax : (float*)0;
#pragma unroll
    for (int i = 0; i < 8; i++) {
        int r = row0 + ty * 8 + i;
        if (r >= N) break;
        if (chunk == 4) {
#pragma unroll
            for (int j = 0; j < 8; j++)
                g_ea[(size_t)r * 128 + 2 * (cc + j) + 1] = acc[i][j] + bv[j];
        } else if (chunk == 2) {
#pragma unroll
            for (int j = 0; j < 8; j++) {
                float v = acc[i][j] + bv[j];
                g_esum[(size_t)r * 64 + cc + j] = v;
                g_ea[(size_t)r * 128 + 2 * (cc + j)] = v;
            }
        } else {
#pragma unroll
            for (int j = 0; j < 8; j++)
                outp[(size_t)r * 64 + cc + j] = acc[i][j] + bv[j];
        }
    }
}

// ---------------- parallel exclusive scan (3 kernels) --------------------------
__global__ void k_scanA(int N) {
    __shared__ int sh[256];
    int t = threadIdx.x;
    int i = blockIdx.x * 256 + t;
    int d = (i < N) ? g_deg[i] : 0;
    sh[t] = d;
    __syncthreads();
    for (int st = 1; st < 256; st <<= 1) {
        int v = (t >= st) ? sh[t - st] : 0;
        __syncthreads();
        sh[t] += v;
        __syncthreads();
    }
    if (i < N) g_off[i] = sh[t] - d;
    if (t == 255) g_part[blockIdx.x] = sh[255];
}
__global__ void k_scanB(int nb, int N) {
    __shared__ int sh[256];
    int t = threadIdx.x;
    int d = (t < nb) ? g_part[t] : 0;
    sh[t] = d;
    __syncthreads();
    for (int st = 1; st < 256; st <<= 1) {
        int v = (t >= st) ? sh[t - st] : 0;
        __syncthreads();
        sh[t] += v;
        __syncthreads();
    }
    if (t < nb) g_part[t] = sh[t] - d;
    if (t == 255) g_off[N] = sh[255];
}
__global__ void k_scanC(int N) {
    int i = blockIdx.x * 256 + threadIdx.x;
    if (i < N) {
        int v = g_off[i] + g_part[blockIdx.x];
        g_off[i] = v;
        g_cur[i] = v;
    }
}

// ---------------- k_scatter: fill CSR adjacency -------------------------------
__global__ void k_scatter(const void* eidx, int E, int N) {
    int is64 = g_is64;
    const long long* p64 = (const long long*)eidx;
    const int* p32 = (const int*)eidx;
    for (int e = blockIdx.x * blockDim.x + threadIdx.x; e < E;
         e += gridDim.x * blockDim.x) {
        int b, en;
        if (is64) { b = (int)p64[e]; en = (int)p64[E + e]; }
        else      { b = p32[e];      en = p32[E + e]; }
        b = clampN(b, N); en = clampN(en, N);
        int pos = atomicAdd(&g_cur[b], 1);
        if (pos < E) g_csr[pos] = en;
    }
}

// ---------------- k_nodeA: pass 1 ---------------------------------------------
// One warp per node. Block-level smem reduction of BN stats + min, then ONE
// global double-atomic per feature per block (kills L2 atomic serialization).
__global__ void k_nodeA(int N) {
    __shared__ float sS1[64];
    __shared__ float sS2[64];
    __shared__ unsigned sMin;
    int tid = threadIdx.x;
    int lane = tid & 31;
    int warp = (blockIdx.x * blockDim.x + tid) >> 5;
    int nwarps = (gridDim.x * blockDim.x) >> 5;
    int f = 2 * lane;

    if (tid < 64) { sS1[tid] = 0.f; sS2[tid] = 0.f; }
    if (tid == 0) sMin = 0xFFFFFFFFu;
    __syncthreads();

    float S1a = 0.f, S1b = 0.f, S2a = 0.f, S2b = 0.f;
    float lmin = 1e30f;

    for (int n = warp; n < N; n += nwarps) {
        int off = g_off[n];
        int dg = g_off[n + 1] - off;
        float2 b = *(const float2*)&g_bsum[n * 64 + f];
        float2 bm = *(const float2*)&g_bmax[n * 64 + f];
        float ssx = 0.f, ssy = 0.f;
        float mxx = -1e30f, mxy = -1e30f;
        float mnx = 1e30f, mny = 1e30f;

        for (int j0 = 0; j0 < dg; j0 += 32) {
            int idx = (j0 + lane < dg) ? g_csr[off + j0 + lane] : 0;
            int cnt = min(32, dg - j0);
            int j = 0;
            for (; j + 4 <= cnt; j += 4) {
                int n0 = __shfl_sync(0xFFFFFFFFu, idx, j);
                int n1 = __shfl_sync(0xFFFFFFFFu, idx, j + 1);
                int n2 = __shfl_sync(0xFFFFFFFFu, idx, j + 2);
                int n3 = __shfl_sync(0xFFFFFFFFu, idx, j + 3);
                float4 q0 = *(const float4*)&g_ea[(size_t)n0 * 128 + 4 * lane];
                float4 q1 = *(const float4*)&g_ea[(size_t)n1 * 128 + 4 * lane];
                float4 q2 = *(const float4*)&g_ea[(size_t)n2 * 128 + 4 * lane];
                float4 q3 = *(const float4*)&g_ea[(size_t)n3 * 128 + 4 * lane];
                ssx += (q0.x + q1.x) + (q2.x + q3.x);
                ssy += (q0.z + q1.z) + (q2.z + q3.z);
                mxx = fmaxf(fmaxf(mxx, q0.y), fmaxf(q1.y, fmaxf(q2.y, q3.y)));
                mxy = fmaxf(fmaxf(mxy, q0.w), fmaxf(q1.w, fmaxf(q2.w, q3.w)));
                mnx = fminf(fminf(mnx, q0.y), fminf(q1.y, fminf(q2.y, q3.y)));
                mny = fminf(fminf(mny, q0.w), fminf(q1.w, fminf(q2.w, q3.w)));
            }
            for (; j < cnt; j++) {
                int nd = __shfl_sync(0xFFFFFFFFu, idx, j);
                float4 q = *(const float4*)&g_ea[(size_t)nd * 128 + 4 * lane];
                ssx += q.x; ssy += q.z;
                mxx = fmaxf(mxx, q.y); mxy = fmaxf(mxy, q.w);
                mnx = fminf(mnx, q.y); mny = fminf(mny, q.w);
            }
        }
        float2 mxo; mxo.x = bm.x + mxx; mxo.y = bm.y + mxy;
        *(float2*)&g_mxraw[n * 64 + f] = mxo;
        if (dg > 0) lmin = fminf(lmin, fminf(bm.x + mnx, bm.y + mny));

        float dco = (float)dg;
        float dci = (float)g_degin[n];
        float2 en = *(const float2*)&g_esum[n * 64 + f];
        S1a += dco * b.x + dci * en.x;
        S1b += dco * b.y + dci * en.y;
        S2a += dco * b.x * b.x + 2.f * b.x * ssx + dci * en.x * en.x;
        S2b += dco * b.y * b.y + 2.f * b.y * ssy + dci * en.y * en.y;
    }
    // block-level reduction (spread-address shared atomics: cheap)
    atomicAdd(&sS1[f], S1a);
    atomicAdd(&sS1[f + 1], S1b);
    atomicAdd(&sS2[f], S2a);
    atomicAdd(&sS2[f + 1], S2b);
#pragma unroll
    for (int s = 16; s; s >>= 1)
        lmin = fminf(lmin, __shfl_xor_sync(0xFFFFFFFFu, lmin, s));
    if (lane == 0) atomicMin(&sMin, enc_f32(lmin));
    __syncthreads();
    if (tid < 64) {
        atomicAdd(&g_S1[tid], (double)sS1[tid]);
        atomicAdd(&g_S2[tid], (double)sS2[tid]);
    }
    if (tid == 0) atomicMin(&g_minenc, sMin);
}

// ---------------- k_params1: edge-BN affine params + min_val -------------------
__global__ void k_params1(const float* __restrict__ gamma,
                          const float* __restrict__ beta, double invE) {
    int fidx = threadIdx.x;  // 64 threads
    double mu = g_S1[fidx] * invE;
    double var = g_S2[fidx] * invE - mu * mu;
    float a = gamma[fidx] * rsqrtf((float)var + EPS_BN);
    g_a[fidx] = a;
    g_c[fidx] = beta[fidx] - (float)mu * a;
    if (fidx == 0) g_minval = dec_f32(g_minenc);
}

// ---------------- k_nodeB: pass 2 ---------------------------------------------
__global__ void k_nodeB(int N) {
    __shared__ float sU1[128];
    __shared__ float sU2[128];
    int tid = threadIdx.x;
    int lane = tid & 31;
    int warp = (blockIdx.x * blockDim.x + tid) >> 5;
    int nwarps = (gridDim.x * blockDim.x) >> 5;
    int f = 2 * lane;

    if (tid < 128) { sU1[tid] = 0.f; sU2[tid] = 0.f; }
    __syncthreads();

    float a0 = g_a[f], a1 = g_a[f + 1];
    float c0 = g_c[f], c1 = g_c[f + 1];
    float minv = g_minval;
    float su1[4] = {0.f, 0.f, 0.f, 0.f};
    float su2[4] = {0.f, 0.f, 0.f, 0.f};

    for (int n = warp; n < N; n += nwarps) {
        int off = g_off[n];
        int dg = g_off[n + 1] - off;
        float2 b = *(const float2*)&g_bsum[n * 64 + f];
        float s0 = 0.f, s1 = 0.f;
        for (int j0 = 0; j0 < dg; j0 += 32) {
            int idx = (j0 + lane < dg) ? g_csr[off + j0 + lane] : 0;
            int cnt = min(32, dg - j0);
            int j = 0;
            for (; j + 4 <= cnt; j += 4) {
                int n0 = __shfl_sync(0xFFFFFFFFu, idx, j);
                int n1 = __shfl_sync(0xFFFFFFFFu, idx, j + 1);
                int n2 = __shfl_sync(0xFFFFFFFFu, idx, j + 2);
                int n3 = __shfl_sync(0xFFFFFFFFu, idx, j + 3);
                float2 e0 = *(const float2*)&g_esum[(size_t)n0 * 64 + f];
                float2 e1 = *(const float2*)&g_esum[(size_t)n1 * 64 + f];
                float2 e2 = *(const float2*)&g_esum[(size_t)n2 * 64 + f];
                float2 e3 = *(const float2*)&g_esum[(size_t)n3 * 64 + f];
                s0 += fmaxf(0.f, fmaf(a0, b.x + e0.x, c0))
                    + fmaxf(0.f, fmaf(a0, b.x + e1.x, c0))
                    + fmaxf(0.f, fmaf(a0, b.x + e2.x, c0))
                    + fmaxf(0.f, fmaf(a0, b.x + e3.x, c0));
                s1 += fmaxf(0.f, fmaf(a1, b.y + e0.y, c1))
                    + fmaxf(0.f, fmaf(a1, b.y + e1.y, c1))
                    + fmaxf(0.f, fmaf(a1, b.y + e2.y, c1))
                    + fmaxf(0.f, fmaf(a1, b.y + e3.y, c1));
            }
            for (; j < cnt; j++) {
                int nd = __shfl_sync(0xFFFFFFFFu, idx, j);
                float2 e = *(const float2*)&g_esum[(size_t)nd * 64 + f];
                s0 += fmaxf(0.f, fmaf(a0, b.x + e.x, c0));
                s1 += fmaxf(0.f, fmaf(a1, b.y + e.y, c1));
            }
        }
        float2 m;
        if (dg > 0) m = *(const float2*)&g_mxraw[n * 64 + f];
        else { m.x = minv; m.y = minv; }

        *(float2*)&g_gath[n * 128 + f] = m;
        float2 sv; sv.x = s0; sv.y = s1;
        *(float2*)&g_gath[n * 128 + 64 + f] = sv;

        su1[0] += m.x; su2[0] += m.x * m.x;
        su1[1] += m.y; su2[1] += m.y * m.y;
        su1[2] += s0;  su2[2] += s0 * s0;
        su1[3] += s1;  su2[3] += s1 * s1;
    }
    atomicAdd(&sU1[f], su1[0]);
    atomicAdd(&sU2[f], su2[0]);
    atomicAdd(&sU1[f + 1], su1[1]);
    atomicAdd(&sU2[f + 1], su2[1]);
    atomicAdd(&sU1[64 + f], su1[2]);
    atomicAdd(&sU2[64 + f], su2[2]);
    atomicAdd(&sU1[64 + f + 1], su1[3]);
    atomicAdd(&sU2[64 + f + 1], su2[3]);
    __syncthreads();
    if (tid < 128) {
        atomicAdd(&g_Su1[tid], (double)sU1[tid]);
        atomicAdd(&g_Su2[tid], (double)sU2[tid]);
    }
}

// ---------------- k_params2: fold node-BN into update GEMM ---------------------
__global__ void k_params2(const float* __restrict__ gamma_u,
                          const float* __restrict__ beta_u,
                          const float* __restrict__ W_u, double invN) {
    __shared__ float sc[128];
    int k = threadIdx.x;  // 128 threads
    double mu = g_Su1[k] * invN;
    double var = g_Su2[k] * invN - mu * mu;
    float au = gamma_u[k] * rsqrtf((float)var + EPS_BN);
    float cu = beta_u[k] - (float)mu * au;
    sc[k] = cu;
    for (int j = 0; j < 64; j++) g_Wp[k * 64 + j] = au * W_u[k * 64 + j];
    __syncthreads();
    if (k < 64) {
        float d = 0.f;
        for (int kk = 0; kk < 128; kk++) d += sc[kk] * W_u[kk * 64 + k];
        g_dbias[k] = d;
    }
}

// ---------------- k_final: out = self_f + relu(gathered @ W' + d) --------------
__global__ void k_final(float* __restrict__ out, int N) {
    __shared__ __align__(16) float sW[128 * 64];
    __shared__ __align__(16) float sG[16 * 128];
    __shared__ __align__(16) float sd[64];
    int tid = threadIdx.x;
    for (int i = tid; i < 128 * 64; i += 256) sW[i] = g_Wp[i];
    if (tid < 64) sd[tid] = g_dbias[tid];
    __syncthreads();

    int ni = tid >> 4;
    int jx = tid & 15;
    int tiles = (N + 15) / 16;
    const float4* W4 = (const float4*)sW;

    for (int t = blockIdx.x; t < tiles; t += gridDim.x) {
        int n0 = t * 16;
        __syncthreads();
        for (int i = tid; i < 16 * 128; i += 256) {
            int gi = n0 * 128 + i;
            sG[i] = (gi < N * 128) ? g_gath[gi] : 0.f;
        }
        __syncthreads();

        float4 acc = {0.f, 0.f, 0.f, 0.f};
#pragma unroll 8
        for (int k = 0; k < 128; k++) {
            float gv = sG[ni * 128 + k];
            float4 w = W4[k * 16 + jx];
            acc.x += gv * w.x;
            acc.y += gv * w.y;
            acc.z += gv * w.z;
            acc.w += gv * w.w;
        }
        int n = n0 + ni;
        if (n < N) {
            float4 dv = ((const float4*)sd)[jx];
            const float4 sf = *(const float4*)&g_self[(size_t)n * 64 + jx * 4];
            float4 o;
            o.x = sf.x + fmaxf(0.f, acc.x + dv.x);
            o.y = sf.y + fmaxf(0.f, acc.y + dv.y);
            o.z = sf.z + fmaxf(0.f, acc.z + dv.z);
            o.w = sf.w + fmaxf(0.f, acc.w + dv.w);
            *(float4*)&out[(size_t)n * 64 + jx * 4] = o;
        }
    }
}

// ---------------- launch ------------------------------------------------------
extern "C" void kernel_launch(void* const* d_in, const int* in_sizes, int n_in,
                              void* d_out, int out_size) {
    const float* n_feat  = (const float*)d_in[0];
    const void*  eidx    = d_in[1];
    const float* W_b     = (const float*)d_in[2];
    const float* b_b     = (const float*)d_in[3];
    const float* gamma_g = (const float*)d_in[4];
    const float* beta_g  = (const float*)d_in[5];
    const float* gamma_u = (const float*)d_in[6];
    const float* beta_u  = (const float*)d_in[7];
    const float* W_u     = (const float*)d_in[8];
    float* out = (float*)d_out;

    int N = in_sizes[0] / 128;
    int E = in_sizes[1] / 2;
    int nscan = (N + 255) / 256;

    k_zero<<<256, 256>>>(eidx);
    k_hist<<<2048, 256>>>(eidx, E, N);
    dim3 ggrid(3, (N + 127) / 128);
    k_gemm<<<ggrid, 256>>>(n_feat, W_b, b_b, N);
    k_scanA<<<nscan, 256>>>(N);
    k_scanB<<<1, 256>>>(nscan, N);
    k_scanC<<<nscan, 256>>>(N);
    k_scatter<<<2048, 256>>>(eidx, E, N);
    k_nodeA<<<1184, 256>>>(N);
    k_params1<<<1, 64>>>(gamma_g, beta_g, 1.0 / (double)E);
    k_nodeB<<<1184, 256>>>(N);
    k_params2<<<1, 128>>>(gamma_u, beta_u, W_u, 1.0 / (double)N);
    k_final<<<1480, 256>>>(out, N);
}